// round 1
// baseline (speedup 1.0000x reference)
#include <cuda_runtime.h>

#define NN   2048
#define FIN  16
#define TT   12
#define FOUT 32
#define BB   8
#define FT   (FIN*TT)   // 192
#define TM   32
#define KT   32

// scratch: Chebyshev supports and S^2
__device__ float g_S [NN*(size_t)NN];
__device__ float g_S2[NN*(size_t)NN];

// ---------------------------------------------------------------------------
// Kernel 1: S = softmax(relu(E E^T), axis=1)   (one block per row)
// ---------------------------------------------------------------------------
__global__ __launch_bounds__(256)
void k_supports(const float* __restrict__ E) {
    const int i   = blockIdx.x;
    const int tid = threadIdx.x;
    __shared__ float ei[FIN];
    __shared__ float row[NN];
    __shared__ float red[8];
    __shared__ float bcast0, bcast1;

    if (tid < FIN) ei[tid] = E[i*FIN + tid];
    __syncthreads();

    float lmax = 0.0f;  // relu output >= 0
    for (int j = tid; j < NN; j += 256) {
        const float4* ej = reinterpret_cast<const float4*>(E + (size_t)j*FIN);
        float dot = 0.f;
        #pragma unroll
        for (int q = 0; q < 4; q++) {
            float4 v = ej[q];
            dot += v.x*ei[q*4+0] + v.y*ei[q*4+1] + v.z*ei[q*4+2] + v.w*ei[q*4+3];
        }
        float r = fmaxf(dot, 0.f);
        row[j] = r;
        lmax = fmaxf(lmax, r);
    }
    #pragma unroll
    for (int o = 16; o > 0; o >>= 1) lmax = fmaxf(lmax, __shfl_xor_sync(0xffffffffu, lmax, o));
    if ((tid & 31) == 0) red[tid >> 5] = lmax;
    __syncthreads();
    if (tid == 0) {
        float m = red[0];
        #pragma unroll
        for (int w = 1; w < 8; w++) m = fmaxf(m, red[w]);
        bcast0 = m;
    }
    __syncthreads();
    const float bmax = bcast0;

    float lsum = 0.f;
    for (int j = tid; j < NN; j += 256) {
        float e = expf(row[j] - bmax);
        row[j] = e;
        lsum += e;
    }
    #pragma unroll
    for (int o = 16; o > 0; o >>= 1) lsum += __shfl_xor_sync(0xffffffffu, lsum, o);
    if ((tid & 31) == 0) red[tid >> 5] = lsum;
    __syncthreads();
    if (tid == 0) {
        float s = 0.f;
        #pragma unroll
        for (int w = 0; w < 8; w++) s += red[w];
        bcast1 = 1.0f / s;
    }
    __syncthreads();
    const float inv = bcast1;
    for (int j = tid; j < NN; j += 256)
        g_S[(size_t)i*NN + j] = row[j] * inv;
}

// ---------------------------------------------------------------------------
// Kernel 2: S2 = S @ S   (128x128 tile, 8x8 per thread, fp32)
// ---------------------------------------------------------------------------
__global__ __launch_bounds__(256)
void k_gemm_ss() {
    const float* A = g_S;
    const float* B = g_S;
    float* C = g_S2;
    __shared__ float As[8][132];
    __shared__ float Bs[8][128];

    const int tid = threadIdx.x;
    const int tx = tid & 15, ty = tid >> 4;
    const int i0 = blockIdx.y * 128, j0 = blockIdx.x * 128;

    float acc[8][8] = {};

    for (int k0 = 0; k0 < NN; k0 += 8) {
        {   // A tile 128x8, transposed into As
            int row = tid >> 1, q = tid & 1;
            float4 av = *reinterpret_cast<const float4*>(A + (size_t)(i0+row)*NN + k0 + q*4);
            As[q*4+0][row] = av.x; As[q*4+1][row] = av.y;
            As[q*4+2][row] = av.z; As[q*4+3][row] = av.w;
        }
        {   // B tile 8x128
            int row = tid >> 5, c4 = tid & 31;
            float4 bv = *reinterpret_cast<const float4*>(B + (size_t)(k0+row)*NN + j0 + c4*4);
            *reinterpret_cast<float4*>(&Bs[row][c4*4]) = bv;
        }
        __syncthreads();
        #pragma unroll
        for (int k = 0; k < 8; k++) {
            float a[8], bb[8];
            #pragma unroll
            for (int i = 0; i < 8; i++) a[i]  = As[k][ty*8+i];
            #pragma unroll
            for (int j = 0; j < 8; j++) bb[j] = Bs[k][tx*8+j];
            #pragma unroll
            for (int i = 0; i < 8; i++)
                #pragma unroll
                for (int j = 0; j < 8; j++)
                    acc[i][j] = fmaf(a[i], bb[j], acc[i][j]);
        }
        __syncthreads();
    }
    #pragma unroll
    for (int i = 0; i < 8; i++) {
        float* crow = C + (size_t)(i0 + ty*8 + i)*NN + j0 + tx*8;
        #pragma unroll
        for (int j = 0; j < 8; j += 4) {
            float4 v = make_float4(acc[i][j], acc[i][j+1], acc[i][j+2], acc[i][j+3]);
            *reinterpret_cast<float4*>(crow + j) = v;
        }
    }
}

// ---------------------------------------------------------------------------
// Kernel 3: fused masked dual-GEMM + theta epilogue + relu
//   rhs1[m,ft] = sum_n  S[n,m]*A[b,n,m]*x[b,n,ft]
//   rhs2[m,ft] = sum_n 2*S2[n,m]*A[b,n,m]*x[b,n,ft]
//   out[m,o,t] = relu( sum_f rhs1*th1 + rhs2*th2 + A[b,m,m]*x[b,m,f,t]*(th0-th2) )
// ---------------------------------------------------------------------------
__global__ __launch_bounds__(256)
void k_main(const float* __restrict__ x, const float* __restrict__ A,
            const float* __restrict__ theta, float* __restrict__ out) {
    extern __shared__ float sm[];
    float* xs = sm;             // KT*FT = 6144 floats
    float* w1 = sm + 6144;      // KT*TM = 1024
    float* w2 = sm + 7168;      // 1024

    const int b   = blockIdx.y;
    const int m0  = blockIdx.x * TM;
    const int tid = threadIdx.x;
    const int tf  = tid & 31;   // 0..31 (ft lane)
    const int tm  = tid >> 5;   // 0..7  (m group)

    float acc1[4][6] = {};
    float acc2[4][6] = {};

    const float* xb = x + (size_t)b*NN*FT;
    const float* Ab = A + (size_t)b*NN*NN;

    for (int n0 = 0; n0 < NN; n0 += KT) {
        // stage x tile (contiguous KT*FT block)
        const float4* x4  = reinterpret_cast<const float4*>(xb + (size_t)n0*FT);
        float4* xs4 = reinterpret_cast<float4*>(xs);
        #pragma unroll
        for (int i = tid; i < KT*FT/4; i += 256) xs4[i] = x4[i];
        // stage masked weight tiles
        #pragma unroll
        for (int i = tid; i < KT*TM; i += 256) {
            int kk = i >> 5;
            int m  = i & 31;
            size_t off = (size_t)(n0 + kk)*NN + m0 + m;
            float a = Ab[off];
            w1[i] = g_S [off] * a;
            w2[i] = 2.0f * g_S2[off] * a;
        }
        __syncthreads();
        #pragma unroll 4
        for (int kk = 0; kk < KT; kk++) {
            float xv[6];
            #pragma unroll
            for (int c = 0; c < 6; c++) xv[c] = xs[kk*FT + tf + 32*c];
            float a1[4], a2[4];
            #pragma unroll
            for (int i = 0; i < 4; i++) { a1[i] = w1[kk*TM + tm*4 + i]; a2[i] = w2[kk*TM + tm*4 + i]; }
            #pragma unroll
            for (int i = 0; i < 4; i++)
                #pragma unroll
                for (int c = 0; c < 6; c++) {
                    acc1[i][c] = fmaf(a1[i], xv[c], acc1[i][c]);
                    acc2[i][c] = fmaf(a2[i], xv[c], acc2[i][c]);
                }
        }
        __syncthreads();
    }

    // ---- epilogue ----
    float* r1   = sm;            // 6144
    float* r2   = sm + 6144;     // 6144
    float* s0   = sm + 12288;    // 6144
    float* th1  = sm + 18432;    // 512
    float* th2  = sm + 18944;    // 512
    float* th02 = sm + 19456;    // 512

    #pragma unroll
    for (int i = 0; i < 4; i++)
        #pragma unroll
        for (int c = 0; c < 6; c++) {
            int m = tm*4 + i, col = tf + 32*c;
            r1[m*FT + col] = acc1[i][c];
            r2[m*FT + col] = acc2[i][c];
        }
    for (int i = tid; i < FIN*FOUT; i += 256) {
        th1[i] = theta[512 + i];
        float t2 = theta[1024 + i];
        th2[i]  = t2;
        th02[i] = theta[i] - t2;   // theta0 - theta2 (identity term)
    }
    for (int i = tid; i < TM*FT; i += 256) {
        int m = i / FT, ftc = i - m*FT;
        float d = Ab[(size_t)(m0+m)*NN + m0 + m];
        s0[i] = d * xb[(size_t)(m0+m)*FT + ftc];
    }
    __syncthreads();

    float* outb = out + (size_t)b*NN*FOUT*TT;
    for (int idx = tid; idx < TM*FOUT*TT; idx += 256) {
        int m = idx / (FOUT*TT);
        int r = idx - m*(FOUT*TT);
        int o = r / TT, t = r - o*TT;
        float val = 0.f;
        #pragma unroll
        for (int f = 0; f < FIN; f++) {
            int ft = f*TT + t;
            val = fmaf(r1[m*FT + ft], th1[f*FOUT + o], val);
            val = fmaf(r2[m*FT + ft], th2[f*FOUT + o], val);
            val = fmaf(s0[m*FT + ft], th02[f*FOUT + o], val);
        }
        outb[(size_t)(m0+m)*FOUT*TT + r] = fmaxf(val, 0.f);
    }
}

// ---------------------------------------------------------------------------
extern "C" void kernel_launch(void* const* d_in, const int* in_sizes, int n_in,
                              void* d_out, int out_size) {
    const float *x = nullptr, *A = nullptr, *E = nullptr, *theta = nullptr;
    for (int i = 0; i < n_in; i++) {
        switch (in_sizes[i]) {
            case BB*NN*FIN*TT:   x     = (const float*)d_in[i]; break;  // 3145728
            case BB*NN*NN:       A     = (const float*)d_in[i]; break;  // 33554432
            case NN*FIN:         E     = (const float*)d_in[i]; break;  // 32768
            case 3*FIN*FOUT:     theta = (const float*)d_in[i]; break;  // 1536
        }
    }
    float* out = (float*)d_out;

    k_supports<<<NN, 256>>>(E);

    dim3 g2(NN/128, NN/128);
    k_gemm_ss<<<g2, 256>>>();

    const int smem3 = 19968 * (int)sizeof(float);  // 79,872 B
    cudaFuncSetAttribute(k_main, cudaFuncAttributeMaxDynamicSharedMemorySize, smem3);
    dim3 g3(NN/TM, BB);
    k_main<<<g3, 256, smem3>>>(x, A, theta, out);
}